// round 17
// baseline (speedup 1.0000x reference)
#include <cuda_runtime.h>
#include <cuda_bf16.h>

// BuzzLoss: B=8192 rows, T=1024 cols.
// Composition of the measured-best pieces across 16 rounds:
//  - R8 body (best ncu time 13.89us): ONE WARP PER ROW, 8 rows/256-thr CTA,
//    16 coalesced LDG.128 with per-segment reduction ON ARRIVAL
//    (p, s1loc, s2loc); c/a die immediately -> 32 regs, ~80% occupancy.
//  - 8 interleaved warp product-scans + 8-deep serial combine.
//  - accLast folded before the reduce -> single-value warp reduce (5 shfls).
//  - per-warp smem store + warp-0 combine -> ONE global atomic per CTA.
//  - separate 1-thread zero kernel (measured cheaper than ticket finalize).

#define FULL_MASK 0xFFFFFFFFu
#define ROWS_PER_CTA 8

__global__ void buzz_zero_kernel(float* out) {
    out[0] = 0.0f;
}

__global__ __launch_bounds__(256)
void buzz_loss_kernel(const float* __restrict__ conf,
                      const float* __restrict__ acc,
                      float* __restrict__ out,
                      float negInvB) {
    const int tid  = threadIdx.x;
    const int lane = tid & 31;
    const int wid  = tid >> 5;
    const size_t row = (size_t)blockIdx.x * ROWS_PER_CTA + wid;

    __shared__ float s_score[ROWS_PER_CTA];

    const float4* c4 = reinterpret_cast<const float4*>(conf + row * 1024) + lane;
    const float4* a4 = reinterpret_cast<const float4*>(acc  + row * 1024) + lane;

    // ---- Phase 1: load + immediate per-segment reduction (c/a die here) ----
    float p[8], s1loc[8], s2loc[8];
    float lastA = 0.0f;

    #pragma unroll
    for (int j = 0; j < 8; j++) {
        const float4 c = c4[j * 32];
        const float4 a = a4[j * 32];

        const float q0 = 1.0f - c.x;
        const float q1 = 1.0f - c.y;
        const float q2 = 1.0f - c.z;
        const float q3 = 1.0f - c.w;

        const float lb0 = c.x;
        const float lb1 = c.y * q0;
        const float lb2 = c.z * (q0 * q1);
        const float lb3 = c.w * (q0 * q1 * q2);

        p[j] = (q0 * q1) * (q2 * q3);
        s1loc[j] = fmaf(lb0, a.x, fmaf(lb1, a.y, fmaf(lb2, a.z, lb3 * a.w)));
        s2loc[j] = (lb0 + lb1) + (lb2 + lb3);

        if (j == 7) lastA = a.w;           // lane 31 -> acc[row, 1023]
    }

    // ---- Phase 2: 8 interleaved warp inclusive product-scans ----
    #pragma unroll
    for (int d = 1; d < 32; d <<= 1) {
        #pragma unroll
        for (int j = 0; j < 8; j++) {
            float v = __shfl_up_sync(FULL_MASK, p[j], d);
            if (lane >= d) p[j] *= v;
        }
    }

    float tot[8], E[8];
    #pragma unroll
    for (int j = 0; j < 8; j++) {
        tot[j] = __shfl_sync(FULL_MASK, p[j], 31);
        E[j]   = __shfl_up_sync(FULL_MASK, p[j], 1);
        if (lane == 0) E[j] = 1.0f;
    }

    // ---- Serial cross-segment chain (8 deep) ----
    float R = 1.0f, s1 = 0.0f, s2 = 0.0f;
    #pragma unroll
    for (int j = 0; j < 8; j++) {
        const float Ej = E[j] * R;
        s1 = fmaf(Ej, s1loc[j], s1);
        s2 = fmaf(Ej, s2loc[j], s2);
        R *= tot[j];
    }

    // ---- Fold accLast, single-value warp reduce (5 shfls) ----
    const float accLast = __shfl_sync(FULL_MASK, lastA, 31);
    float contrib = fmaf(-accLast, s2, s1);
    if (lane == 31) contrib += accLast;

    #pragma unroll
    for (int d = 16; d >= 1; d >>= 1) {
        contrib += __shfl_down_sync(FULL_MASK, contrib, d);
    }

    if (lane == 0) s_score[wid] = contrib;
    __syncthreads();

    // ---- Warp 0: combine 8 row scores, ONE global atomic per CTA ----
    if (wid == 0) {
        float t = (lane < ROWS_PER_CTA) ? s_score[lane] : 0.0f;
        #pragma unroll
        for (int d = 4; d >= 1; d >>= 1) {
            t += __shfl_down_sync(FULL_MASK, t, d);
        }
        if (lane == 0) {
            atomicAdd(out, t * negInvB);
        }
    }
}

extern "C" void kernel_launch(void* const* d_in, const int* in_sizes, int n_in,
                              void* d_out, int out_size) {
    const float* conf = (const float*)d_in[0];
    const float* acc  = (const float*)d_in[1];
    float* out = (float*)d_out;

    const int total = in_sizes[0];
    const int T = 1024;
    const int B = total / T;

    buzz_zero_kernel<<<1, 1>>>(out);
    buzz_loss_kernel<<<B / ROWS_PER_CTA, 256>>>(conf, acc, out,
                                                -1.0f / (float)B);
}